// round 5
// baseline (speedup 1.0000x reference)
#include <cuda_runtime.h>
#include <cuda_bf16.h>
#include <float.h>

// B=4. Per query: argmin over anchors of d' = a2 - 2*q.a (same argmin as
// squared distance; first-index tie-break via (fkey<<32|idx) min), then count
// dot(diff, summed face normal) < 0 within MAX_DIST. Normal normalization is
// a positive scaling -> sign unchanged -> raw summed face normals suffice.
//
// NN via uniform 32^3 grid: counting-sort anchors AND queries by cell,
// expanding Chebyshev-ring search with exact per-cell box-distance pruning.

#define NB      4
#define GDIM    32
#define NCELL   (GDIM * GDIM * GDIM)
#define NCELL1  (NCELL + 1)
#define MAXA    8192
#define MAXQ    16384
#define GX0     (-5.0f)
#define CH      0.3125f
#define INVH    3.2f
#define MARGIN  1e-2f

typedef unsigned long long u64;

__device__ int    g_Acnt[NB * NCELL];
__device__ int    g_Qcnt[NB * NCELL];
__device__ int    g_Astart[NB * NCELL1];
__device__ int    g_Acur[NB * NCELL];
__device__ int    g_Qstart[NB * NCELL1];
__device__ int    g_Qcur[NB * NCELL];
__device__ float4 g_Wp[NB * MAXA];    // sorted: (wx,wy,wz,ww) = (-2a, a2)
__device__ int    g_Aidx[NB * MAXA];  // sorted slot -> original anchor idx
__device__ float4 g_Qs[NB * MAXQ];    // sorted: (qx,qy,qz,q2)
__device__ float  g_acc[NB * MAXA * 3];

__device__ __forceinline__ int clampi(int v, int lo, int hi) {
    return v < lo ? lo : (v > hi ? hi : v);
}
__device__ __forceinline__ void cell_of(float x, float y, float z,
                                        int& cx, int& cy, int& cz) {
    cx = clampi(__float2int_rd((x - GX0) * INVH), 0, GDIM - 1);
    cy = clampi(__float2int_rd((y - GX0) * INVH), 0, GDIM - 1);
    cz = clampi(__float2int_rd((z - GX0) * INVH), 0, GDIM - 1);
}
// Monotone float-bits -> u32 key (smaller float -> smaller key). No NaNs.
__device__ __forceinline__ unsigned fkey(float f) {
    unsigned b = __float_as_uint(f);
    return (b & 0x80000000u) ? ~b : (b | 0x80000000u);
}

// ---------------------------------------------------------------------------
// K0: zero counters, normals accumulator, output
// ---------------------------------------------------------------------------
__global__ void zero_kernel(float* __restrict__ out)
{
    int i = blockIdx.x * blockDim.x + threadIdx.x;
    if (i < NB) out[i] = 0.0f;
    if (i < NB * NCELL) { g_Acnt[i] = 0; g_Qcnt[i] = 0; }
    if (i < NB * MAXA * 3) g_acc[i] = 0.0f;
}

// ---------------------------------------------------------------------------
// K1: count anchors and queries per cell
// ---------------------------------------------------------------------------
__global__ void count_kernel(const float* __restrict__ anchor,
                             const float* __restrict__ query,
                             int Na, int Nq)
{
    int i = blockIdx.x * blockDim.x + threadIdx.x;
    int totA = NB * Na;
    if (i < totA) {
        int b = i / Na;
        int cx, cy, cz;
        cell_of(anchor[3 * i], anchor[3 * i + 1], anchor[3 * i + 2], cx, cy, cz);
        atomicAdd(&g_Acnt[b * NCELL + (cz * GDIM + cy) * GDIM + cx], 1);
    }
    int j = i - totA;
    if (j >= 0 && j < NB * Nq) {
        int b = j / Nq;
        int cx, cy, cz;
        cell_of(query[3 * j], query[3 * j + 1], query[3 * j + 2], cx, cy, cz);
        atomicAdd(&g_Qcnt[b * NCELL + (cz * GDIM + cy) * GDIM + cx], 1);
    }
}

// ---------------------------------------------------------------------------
// K2: exclusive scan of 32768 counts per (batch, kind). 8 blocks x 1024 thr.
// ---------------------------------------------------------------------------
__global__ void __launch_bounds__(1024)
scan_kernel()
{
    __shared__ int sp[1024];
    int which = blockIdx.x;            // 0..3 anchors, 4..7 queries
    int b = which & 3;
    bool isQ = which >= 4;
    const int* cnt = (isQ ? g_Qcnt : g_Acnt) + b * NCELL;
    int* start = (isQ ? g_Qstart : g_Astart) + b * NCELL1;
    int* cur   = (isQ ? g_Qcur   : g_Acur)   + b * NCELL;

    int t = threadIdx.x;
    int c0 = t * 32;
    int loc[32];
    int s = 0;
    #pragma unroll
    for (int i = 0; i < 32; i++) { loc[i] = s; s += cnt[c0 + i]; }
    sp[t] = s;
    __syncthreads();
    for (int off = 1; off < 1024; off <<= 1) {
        int v = (t >= off) ? sp[t - off] : 0;
        __syncthreads();
        sp[t] += v;
        __syncthreads();
    }
    int base = sp[t] - s;              // exclusive offset for this thread
    #pragma unroll
    for (int i = 0; i < 32; i++) {
        int v = base + loc[i];
        start[c0 + i] = v;
        cur[c0 + i] = v;
    }
    if (t == 1023) start[NCELL] = sp[1023];
}

// ---------------------------------------------------------------------------
// K3: scatter anchors (weights + original idx) and queries into sorted order
// ---------------------------------------------------------------------------
__global__ void scatter_kernel(const float* __restrict__ anchor,
                               const float* __restrict__ query,
                               int Na, int Nq)
{
    int i = blockIdx.x * blockDim.x + threadIdx.x;
    int totA = NB * Na;
    if (i < totA) {
        int b = i / Na;
        int a = i - b * Na;
        float x = anchor[3 * i], y = anchor[3 * i + 1], z = anchor[3 * i + 2];
        int cx, cy, cz;
        cell_of(x, y, z, cx, cy, cz);
        int c = (cz * GDIM + cy) * GDIM + cx;
        int pos = atomicAdd(&g_Acur[b * NCELL + c], 1);
        g_Wp[b * MAXA + pos] = make_float4(-2.0f * x, -2.0f * y, -2.0f * z,
                                           x * x + y * y + z * z);
        g_Aidx[b * MAXA + pos] = a;
    }
    int j = i - totA;
    if (j >= 0 && j < NB * Nq) {
        int b = j / Nq;
        float x = query[3 * j], y = query[3 * j + 1], z = query[3 * j + 2];
        int cx, cy, cz;
        cell_of(x, y, z, cx, cy, cz);
        int c = (cz * GDIM + cy) * GDIM + cx;
        int pos = atomicAdd(&g_Qcur[b * NCELL + c], 1);
        g_Qs[b * MAXQ + pos] = make_float4(x, y, z, x * x + y * y + z * z);
    }
}

// ---------------------------------------------------------------------------
// K4: face normals scatter-add (by original anchor index)
// ---------------------------------------------------------------------------
__global__ void face_kernel(const float* __restrict__ anchor,
                            const int* __restrict__ faces, int Na, int F)
{
    int i = blockIdx.x * blockDim.x + threadIdx.x;
    if (i >= NB * F) return;
    int b = i / F;
    int f = i - b * F;

    int i0 = faces[3 * f + 0];
    int i1 = faces[3 * f + 1];
    int i2 = faces[3 * f + 2];

    const float* base = anchor + (size_t)b * Na * 3;
    float v0x = base[3 * i0 + 0], v0y = base[3 * i0 + 1], v0z = base[3 * i0 + 2];
    float v1x = base[3 * i1 + 0], v1y = base[3 * i1 + 1], v1z = base[3 * i1 + 2];
    float v2x = base[3 * i2 + 0], v2y = base[3 * i2 + 1], v2z = base[3 * i2 + 2];

    float e1x = v1x - v0x, e1y = v1y - v0y, e1z = v1z - v0z;
    float e2x = v2x - v0x, e2y = v2y - v0y, e2z = v2z - v0z;

    float nx = e1y * e2z - e1z * e2y;
    float ny = e1z * e2x - e1x * e2z;
    float nz = e1x * e2y - e1y * e2x;

    float* acc = g_acc + (size_t)b * MAXA * 3;
    atomicAdd(&acc[3 * i0 + 0], nx);
    atomicAdd(&acc[3 * i0 + 1], ny);
    atomicAdd(&acc[3 * i0 + 2], nz);
    atomicAdd(&acc[3 * i1 + 0], nx);
    atomicAdd(&acc[3 * i1 + 1], ny);
    atomicAdd(&acc[3 * i1 + 2], nz);
    atomicAdd(&acc[3 * i2 + 0], nx);
    atomicAdd(&acc[3 * i2 + 1], ny);
    atomicAdd(&acc[3 * i2 + 2], nz);
}

// ---------------------------------------------------------------------------
// K5: grid-pruned NN + collision predicate + count. One thread per sorted
// query slot (spatially coherent within a warp).
// ---------------------------------------------------------------------------
__global__ void __launch_bounds__(256)
nn_kernel(const float* __restrict__ anchor, float* __restrict__ out,
          int Nq, int Na)
{
    int b = blockIdx.y;
    int s = blockIdx.x * 256 + threadIdx.x;
    bool valid = (s < Nq);

    float qx = 0.f, qy = 0.f, qz = 0.f, q2 = 0.f;
    if (valid) {
        float4 qv = g_Qs[b * MAXQ + s];
        qx = qv.x; qy = qv.y; qz = qv.z; q2 = qv.w;
    }

    const int*    Astart = g_Astart + b * NCELL1;
    const float4* Wp     = g_Wp + b * MAXA;
    const int*    Aidx   = g_Aidx + b * MAXA;

    float dbest = FLT_MAX;
    u64 kbest = 0xFFFFFFFFFFFFFFFFull;

    if (valid) {
        int cx, cy, cz;
        cell_of(qx, qy, qz, cx, cy, cz);

        for (int r = 0; r < GDIM; r++) {
            int x0 = clampi(cx - r, 0, GDIM - 1), x1 = clampi(cx + r, 0, GDIM - 1);
            int y0 = clampi(cy - r, 0, GDIM - 1), y1 = clampi(cy + r, 0, GDIM - 1);
            int z0 = clampi(cz - r, 0, GDIM - 1), z1 = clampi(cz + r, 0, GDIM - 1);

            for (int z = z0; z <= z1; z++) {
                int adz = abs(z - cz);
                for (int y = y0; y <= y1; y++) {
                    int ady = abs(y - cy);
                    int my = max(adz, ady);
                    for (int x = x0; x <= x1; x++) {
                        int ch = max(my, abs(x - cx));
                        if (ch != r) continue;      // ring shell only

                        // exact box-distance lower bound for this cell
                        float bx = GX0 + x * CH;
                        float by = GX0 + y * CH;
                        float bz = GX0 + z * CH;
                        float ddx = fmaxf(fmaxf(bx - qx, qx - (bx + CH)), 0.f);
                        float ddy = fmaxf(fmaxf(by - qy, qy - (by + CH)), 0.f);
                        float ddz = fmaxf(fmaxf(bz - qz, qz - (bz + CH)), 0.f);
                        float d2c = ddx * ddx + ddy * ddy + ddz * ddz;
                        if (d2c > dbest + q2 + MARGIN) continue;

                        int c = (z * GDIM + y) * GDIM + x;
                        int p0 = Astart[c];
                        int p1 = Astart[c + 1];
                        for (int p = p0; p < p1; p++) {
                            float4 w = Wp[p];
                            float d = fmaf(w.x, qx,
                                      fmaf(w.y, qy,
                                      fmaf(w.z, qz, w.w)));
                            u64 key = ((u64)fkey(d) << 32) | (unsigned)Aidx[p];
                            if (key < kbest) { kbest = key; dbest = d; }
                        }
                    }
                }
            }
            float L = r * CH;   // lower bound for ring r+1 (cells >= r cells away)
            if (L * L > dbest + q2 + MARGIN) break;
        }
    }

    int best = valid ? (int)(unsigned)(kbest & 0xFFFFFFFFull) : 0;

    const float* ap = anchor + ((size_t)b * Na + best) * 3;
    float dx = qx - ap[0];
    float dy = qy - ap[1];
    float dz = qz - ap[2];

    const float* npx = g_acc + ((size_t)b * MAXA + best) * 3;
    float dot = dx * npx[0] + dy * npx[1] + dz * npx[2];
    float l2  = sqrtf(dx * dx + dy * dy + dz * dz);

    int coll = (valid && (l2 <= 5.0f) && (dot < 0.0f)) ? 1 : 0;
    unsigned m = __ballot_sync(0xFFFFFFFFu, coll);
    if ((threadIdx.x & 31) == 0 && m)
        atomicAdd(&out[b], (float)__popc(m));
}

// ---------------------------------------------------------------------------
extern "C" void kernel_launch(void* const* d_in, const int* in_sizes, int n_in,
                              void* d_out, int out_size)
{
    const float* query  = (const float*)d_in[0];
    const float* anchor = (const float*)d_in[1];
    const int*   faces  = (const int*)d_in[2];
    float* out = (float*)d_out;

    int Nq = in_sizes[0] / (NB * 3);
    int Na = in_sizes[1] / (NB * 3);
    int F  = in_sizes[2] / 3;

    int zn = NB * NCELL;
    if (NB * MAXA * 3 > zn) zn = NB * MAXA * 3;
    zero_kernel<<<(zn + 255) / 256, 256>>>(out);

    int cn = NB * (Na + Nq);
    count_kernel<<<(cn + 255) / 256, 256>>>(anchor, query, Na, Nq);

    scan_kernel<<<8, 1024>>>();

    scatter_kernel<<<(cn + 255) / 256, 256>>>(anchor, query, Na, Nq);

    face_kernel<<<(NB * F + 255) / 256, 256>>>(anchor, faces, Na, F);

    dim3 ngrid((Nq + 255) / 256, NB);
    nn_kernel<<<ngrid, 256>>>(anchor, out, Nq, Na);
}

// round 6
// speedup vs baseline: 1.2148x; 1.2148x over previous
#include <cuda_runtime.h>
#include <cuda_bf16.h>
#include <float.h>

// B=4. Per query: argmin over anchors of d' = a2 - 2*q.a (same argmin as
// squared distance; exact first-index tie-break via (fkey<<32|idx) min),
// then count dot(diff, summed face normal) < 0 within MAX_DIST. Normal
// normalization is a positive scaling -> sign unchanged -> raw summed face
// normals suffice.
//
// NN: queries counting-sorted by 32^3 cell so warps are spatially tight.
// Per warp: centroid c + radius R; pass1 lane-parallel min |a-c|; sound
// filter T = dmin_c + 2R + margin; pass2 ballot-compact survivors to smem;
// per-lane exact eval of candidates only. Filter is conservative => exact.

#define NB      4
#define GDIM    32
#define NCELL   (GDIM * GDIM * GDIM)
#define MAXA    8192
#define MAXQ    16384
#define GX0     (-5.0f)
#define INVH    3.2f

typedef unsigned long long u64;

__device__ int    g_Qcnt[NB * NCELL];
__device__ int    g_Qstart[NB * NCELL];
__device__ int    g_Qcur[NB * NCELL];
__device__ float4 g_Qs[NB * MAXQ];          // sorted queries (x,y,z,0)
__device__ float  g_acc[NB * MAXA * 3];     // summed face normals (orig idx)

__device__ __forceinline__ int clampi(int v, int lo, int hi) {
    return v < lo ? lo : (v > hi ? hi : v);
}
__device__ __forceinline__ int cell_of(float x, float y, float z) {
    int cx = clampi(__float2int_rd((x - GX0) * INVH), 0, GDIM - 1);
    int cy = clampi(__float2int_rd((y - GX0) * INVH), 0, GDIM - 1);
    int cz = clampi(__float2int_rd((z - GX0) * INVH), 0, GDIM - 1);
    return (cz * GDIM + cy) * GDIM + cx;
}
// Monotone float-bits -> u32 key (smaller float -> smaller key). No NaNs.
__device__ __forceinline__ unsigned fkey(float f) {
    unsigned b = __float_as_uint(f);
    return (b & 0x80000000u) ? ~b : (b | 0x80000000u);
}

// ---------------------------------------------------------------------------
// K0: zero out, cell counters, normal accumulators
// ---------------------------------------------------------------------------
__global__ void zero_kernel(float* __restrict__ out)
{
    int i = blockIdx.x * blockDim.x + threadIdx.x;
    if (i < NB) out[i] = 0.0f;
    if (i < NB * NCELL) g_Qcnt[i] = 0;
    if (i < NB * MAXA * 3) g_acc[i] = 0.0f;
}

// ---------------------------------------------------------------------------
// K1: count queries per cell
// ---------------------------------------------------------------------------
__global__ void count_kernel(const float* __restrict__ query, int Nq)
{
    int i = blockIdx.x * blockDim.x + threadIdx.x;
    if (i >= NB * Nq) return;
    int b = i / Nq;
    int c = cell_of(query[3 * i], query[3 * i + 1], query[3 * i + 2]);
    atomicAdd(&g_Qcnt[b * NCELL + c], 1);
}

// ---------------------------------------------------------------------------
// K2: exclusive scan of 32768 counts per batch (1 block/batch, 1024 thr)
// ---------------------------------------------------------------------------
__global__ void __launch_bounds__(1024)
scan_kernel()
{
    __shared__ int sp[1024];
    int b = blockIdx.x;
    const int* cnt = g_Qcnt + b * NCELL;
    int* start = g_Qstart + b * NCELL;
    int* cur   = g_Qcur   + b * NCELL;

    int t = threadIdx.x;
    int c0 = t * 32;
    int loc[32];
    int s = 0;
    #pragma unroll
    for (int i = 0; i < 32; i++) { loc[i] = s; s += cnt[c0 + i]; }
    sp[t] = s;
    __syncthreads();
    for (int off = 1; off < 1024; off <<= 1) {
        int v = (t >= off) ? sp[t - off] : 0;
        __syncthreads();
        sp[t] += v;
        __syncthreads();
    }
    int base = sp[t] - s;
    #pragma unroll
    for (int i = 0; i < 32; i++) {
        int v = base + loc[i];
        start[c0 + i] = v;
        cur[c0 + i] = v;
    }
}

// ---------------------------------------------------------------------------
// K3: scatter queries into cell-sorted order
// ---------------------------------------------------------------------------
__global__ void scatter_kernel(const float* __restrict__ query, int Nq)
{
    int i = blockIdx.x * blockDim.x + threadIdx.x;
    if (i >= NB * Nq) return;
    int b = i / Nq;
    float x = query[3 * i], y = query[3 * i + 1], z = query[3 * i + 2];
    int c = cell_of(x, y, z);
    int pos = atomicAdd(&g_Qcur[b * NCELL + c], 1);
    g_Qs[b * MAXQ + pos] = make_float4(x, y, z, 0.0f);
}

// ---------------------------------------------------------------------------
// K4: face normals scatter-add (by original anchor index)
// ---------------------------------------------------------------------------
__global__ void face_kernel(const float* __restrict__ anchor,
                            const int* __restrict__ faces, int Na, int F)
{
    int i = blockIdx.x * blockDim.x + threadIdx.x;
    if (i >= NB * F) return;
    int b = i / F;
    int f = i - b * F;

    int i0 = faces[3 * f + 0];
    int i1 = faces[3 * f + 1];
    int i2 = faces[3 * f + 2];

    const float* base = anchor + (size_t)b * Na * 3;
    float v0x = base[3 * i0 + 0], v0y = base[3 * i0 + 1], v0z = base[3 * i0 + 2];
    float v1x = base[3 * i1 + 0], v1y = base[3 * i1 + 1], v1z = base[3 * i1 + 2];
    float v2x = base[3 * i2 + 0], v2y = base[3 * i2 + 1], v2z = base[3 * i2 + 2];

    float e1x = v1x - v0x, e1y = v1y - v0y, e1z = v1z - v0z;
    float e2x = v2x - v0x, e2y = v2y - v0y, e2z = v2z - v0z;

    float nx = e1y * e2z - e1z * e2y;
    float ny = e1z * e2x - e1x * e2z;
    float nz = e1x * e2y - e1y * e2x;

    float* acc = g_acc + (size_t)b * MAXA * 3;
    atomicAdd(&acc[3 * i0 + 0], nx);
    atomicAdd(&acc[3 * i0 + 1], ny);
    atomicAdd(&acc[3 * i0 + 2], nz);
    atomicAdd(&acc[3 * i1 + 0], nx);
    atomicAdd(&acc[3 * i1 + 1], ny);
    atomicAdd(&acc[3 * i1 + 2], nz);
    atomicAdd(&acc[3 * i2 + 0], nx);
    atomicAdd(&acc[3 * i2 + 1], ny);
    atomicAdd(&acc[3 * i2 + 2], nz);
}

// ---------------------------------------------------------------------------
// K5: warp-cooperative filtered NN + collision count.
// 128 threads = 4 warps; each warp owns 32 consecutive sorted queries.
// ---------------------------------------------------------------------------
#define NN_THREADS 128
#define CHUNK 128      // anchors per filter chunk (4 per lane)

__global__ void __launch_bounds__(NN_THREADS)
nn_kernel(const float* __restrict__ anchor, float* __restrict__ out,
          int Nq, int Na)
{
    __shared__ float4 sW[4][CHUNK];
    __shared__ int    sI[4][CHUNK];

    int b = blockIdx.y;
    int tid = threadIdx.x;
    int wid = tid >> 5;
    int lane = tid & 31;
    int s = blockIdx.x * NN_THREADS + tid;
    bool valid = (s < Nq);
    int sc = valid ? s : (Nq - 1);

    float4 qv = g_Qs[b * MAXQ + sc];
    float qx = qv.x, qy = qv.y, qz = qv.z;

    // warp centroid
    float cx = qx, cy = qy, cz = qz;
    #pragma unroll
    for (int o = 16; o >= 1; o >>= 1) {
        cx += __shfl_xor_sync(0xFFFFFFFFu, cx, o);
        cy += __shfl_xor_sync(0xFFFFFFFFu, cy, o);
        cz += __shfl_xor_sync(0xFFFFFFFFu, cz, o);
    }
    cx *= 0.03125f; cy *= 0.03125f; cz *= 0.03125f;

    // warp radius
    float rx = qx - cx, ry = qy - cy, rz = qz - cz;
    float r2 = rx * rx + ry * ry + rz * rz;
    #pragma unroll
    for (int o = 16; o >= 1; o >>= 1)
        r2 = fmaxf(r2, __shfl_xor_sync(0xFFFFFFFFu, r2, o));
    float R = sqrtf(r2);

    const float* A = anchor + (size_t)b * Na * 3;

    // pass 1: min squared distance anchor -> centroid (lane-parallel)
    float dmin2 = FLT_MAX;
    for (int i = lane; i < Na; i += 32) {
        float ax = A[3 * i] - cx;
        float ay = A[3 * i + 1] - cy;
        float az = A[3 * i + 2] - cz;
        dmin2 = fminf(dmin2, ax * ax + ay * ay + az * az);
    }
    #pragma unroll
    for (int o = 16; o >= 1; o >>= 1)
        dmin2 = fminf(dmin2, __shfl_xor_sync(0xFFFFFFFFu, dmin2, o));

    float T = sqrtf(dmin2) + 2.0f * R + 1e-3f;
    float T2 = T * T + 1e-3f;

    // pass 2: chunked filter + compact + exact candidate eval
    u64 kbest = 0xFFFFFFFFFFFFFFFFull;
    for (int base = 0; base < Na; base += CHUNK) {
        int cnt = 0;
        #pragma unroll
        for (int sub = 0; sub < 4; sub++) {
            int i = base + sub * 32 + lane;
            bool ok = false;
            float ax = 0.f, ay = 0.f, az = 0.f;
            if (i < Na) {
                ax = A[3 * i]; ay = A[3 * i + 1]; az = A[3 * i + 2];
                float ux = ax - cx, uy = ay - cy, uz = az - cz;
                ok = (ux * ux + uy * uy + uz * uz) <= T2;
            }
            unsigned bal = __ballot_sync(0xFFFFFFFFu, ok);
            if (ok) {
                int pos = cnt + __popc(bal & ((1u << lane) - 1u));
                sW[wid][pos] = make_float4(-2.0f * ax, -2.0f * ay, -2.0f * az,
                                           ax * ax + ay * ay + az * az);
                sI[wid][pos] = i;
            }
            cnt += __popc(bal);
        }
        __syncwarp();
        for (int k = 0; k < cnt; k++) {
            float4 w = sW[wid][k];
            float d = fmaf(w.x, qx, fmaf(w.y, qy, fmaf(w.z, qz, w.w)));
            u64 key = ((u64)fkey(d) << 32) | (unsigned)sI[wid][k];
            if (key < kbest) kbest = key;
        }
        __syncwarp();
    }

    int best = (int)(unsigned)(kbest & 0xFFFFFFFFull);

    // gather nearest anchor + raw normal, evaluate predicate
    const float* ap = A + (size_t)best * 3;
    float dx = qx - ap[0];
    float dy = qy - ap[1];
    float dz = qz - ap[2];

    const float* npx = g_acc + ((size_t)b * MAXA + best) * 3;
    float dot = dx * npx[0] + dy * npx[1] + dz * npx[2];
    float l2  = sqrtf(dx * dx + dy * dy + dz * dz);

    int coll = (valid && (l2 <= 5.0f) && (dot < 0.0f)) ? 1 : 0;
    unsigned m = __ballot_sync(0xFFFFFFFFu, coll);
    if (lane == 0 && m)
        atomicAdd(&out[b], (float)__popc(m));
}

// ---------------------------------------------------------------------------
extern "C" void kernel_launch(void* const* d_in, const int* in_sizes, int n_in,
                              void* d_out, int out_size)
{
    const float* query  = (const float*)d_in[0];
    const float* anchor = (const float*)d_in[1];
    const int*   faces  = (const int*)d_in[2];
    float* out = (float*)d_out;

    int Nq = in_sizes[0] / (NB * 3);
    int Na = in_sizes[1] / (NB * 3);
    int F  = in_sizes[2] / 3;

    int zn = NB * NCELL;
    if (NB * MAXA * 3 > zn) zn = NB * MAXA * 3;
    zero_kernel<<<(zn + 255) / 256, 256>>>(out);

    count_kernel<<<(NB * Nq + 255) / 256, 256>>>(query, Nq);

    scan_kernel<<<NB, 1024>>>();

    scatter_kernel<<<(NB * Nq + 255) / 256, 256>>>(query, Nq);

    face_kernel<<<(NB * F + 255) / 256, 256>>>(anchor, faces, Na, F);

    dim3 ngrid((Nq + NN_THREADS - 1) / NN_THREADS, NB);
    nn_kernel<<<ngrid, NN_THREADS>>>(anchor, out, Nq, Na);
}